// round 3
// baseline (speedup 1.0000x reference)
#include <cuda_runtime.h>
#include <cuda_fp16.h>
#include <cstdint>

#define TT 256
#define BB 512
#define FF 64
#define UU 128
#define NG 512           // 4*U
#define TB (TT*BB)       // 131072

// ---------- static device scratch (no allocation) ----------
__device__ __half g_x16[(size_t)TB * FF];   // x time-major fp16 [t][b][f]
__device__ float  g_xz [(size_t)TB * NG];   // xz scratch fp32 (reused both layers)
__device__ __half g_hs [(size_t)TB * UU];   // layer-1 hidden states [t][b][u]
__device__ float  g_hlast[BB * UU];         // layer-2 final h

// ---------- helpers ----------
__device__ __forceinline__ void mma16816(float* d, const uint32_t* a, uint32_t b0, uint32_t b1) {
    asm volatile(
        "mma.sync.aligned.m16n8k16.row.col.f32.f16.f16.f32 "
        "{%0,%1,%2,%3}, {%4,%5,%6,%7}, {%8,%9}, {%0,%1,%2,%3};"
        : "+f"(d[0]), "+f"(d[1]), "+f"(d[2]), "+f"(d[3])
        : "r"(a[0]), "r"(a[1]), "r"(a[2]), "r"(a[3]), "r"(b0), "r"(b1));
}
__device__ __forceinline__ void ldsm4(uint32_t* a, const __half* p) {
    uint32_t addr = (uint32_t)__cvta_generic_to_shared(p);
    asm volatile("ldmatrix.sync.aligned.m8n8.x4.shared.b16 {%0,%1,%2,%3}, [%4];"
                 : "=r"(a[0]), "=r"(a[1]), "=r"(a[2]), "=r"(a[3]) : "r"(addr));
}
__device__ __forceinline__ float sigm(float x) {
    return __fdividef(1.f, 1.f + __expf(-x));
}
__device__ __forceinline__ float tanhe(float x) {
    return 1.f - 2.f * __fdividef(1.f, 1.f + __expf(2.f * x));
}

// ---------- convert x [B][T][F] fp32 -> [T][B][F] fp16 ----------
__global__ void k_prep(const float* __restrict__ x) {
    int n = TB * FF;
    for (int idx = blockIdx.x * blockDim.x + threadIdx.x; idx < n; idx += gridDim.x * blockDim.x) {
        int f = idx & 63;
        int b = (idx >> 6) & 511;
        int t = idx >> 15;
        g_x16[idx] = __float2half(x[((size_t)b * TT + t) * FF + f]);
    }
}

// ---------- GEMM: out[M][512] = A(fp16)[M][K] @ W(fp32)[K][512] + bias ----------
// persistent CTAs; tile M=64 x N=512; 8 warps x 64 cols; W packed half2-along-k in smem.
template <int K>
__global__ void __launch_bounds__(256, 1)
k_gemm(const __half* __restrict__ A, const float* __restrict__ Wg,
       const float* __restrict__ bias, float* __restrict__ out, int Mtiles) {
    extern __shared__ char sm[];
    uint32_t* Wp = (uint32_t*)sm;                                   // [K/2][520] half2
    __half*   As = (__half*)(sm + (K / 2) * 520 * 4);               // [64][K+8]
    float*    bs = (float*)(sm + (K / 2) * 520 * 4 + 64 * (K + 8) * 2);
    const int ldA = K + 8;
    int tid = threadIdx.x, w = tid >> 5, lane = tid & 31;

    for (int i = tid; i < (K / 2) * NG; i += 256) {
        int kk = i >> 9, n = i & 511;
        __half2 h2 = __floats2half2_rn(Wg[(size_t)(2 * kk) * NG + n],
                                       Wg[(size_t)(2 * kk + 1) * NG + n]);
        Wp[kk * 520 + n] = *(uint32_t*)&h2;
    }
    for (int i = tid; i < NG; i += 256) bs[i] = bias[i];

    for (int tile = blockIdx.x; tile < Mtiles; tile += gridDim.x) {
        int m0 = tile * 64;
        __syncthreads();
        for (int i = tid; i < 64 * (K / 8); i += 256) {
            int r = i / (K / 8), c = (i % (K / 8)) * 8;
            *(uint4*)&As[r * ldA + c] = *(const uint4*)&A[(size_t)(m0 + r) * K + c];
        }
        __syncthreads();

        float acc[4][8][4];
#pragma unroll
        for (int mt = 0; mt < 4; mt++)
#pragma unroll
            for (int nt = 0; nt < 8; nt++)
#pragma unroll
                for (int q = 0; q < 4; q++) acc[mt][nt][q] = 0.f;

#pragma unroll
        for (int kt = 0; kt < K / 16; kt++) {
            uint32_t a[4][4];
#pragma unroll
            for (int mt = 0; mt < 4; mt++) {
                int row = mt * 16 + (lane & 7) + ((lane >> 3) & 1) * 8;
                int col = kt * 16 + (lane >> 4) * 8;
                ldsm4(a[mt], &As[row * ldA + col]);
            }
            int c4 = lane & 3;
#pragma unroll
            for (int nt = 0; nt < 8; nt++) {
                int n = w * 64 + nt * 8 + (lane >> 2);
                uint32_t b0 = Wp[(kt * 8 + c4) * 520 + n];
                uint32_t b1 = Wp[(kt * 8 + 4 + c4) * 520 + n];
#pragma unroll
                for (int mt = 0; mt < 4; mt++) mma16816(acc[mt][nt], a[mt], b0, b1);
            }
        }
#pragma unroll
        for (int mt = 0; mt < 4; mt++) {
            int r0 = m0 + mt * 16 + (lane >> 2);
#pragma unroll
            for (int nt = 0; nt < 8; nt++) {
                int cc = w * 64 + nt * 8 + (lane & 3) * 2;
                float bb0 = bs[cc], bb1 = bs[cc + 1];
                *(float2*)&out[(size_t)r0 * NG + cc] =
                    make_float2(acc[mt][nt][0] + bb0, acc[mt][nt][1] + bb1);
                *(float2*)&out[(size_t)(r0 + 8) * NG + cc] =
                    make_float2(acc[mt][nt][2] + bb0, acc[mt][nt][3] + bb1);
            }
        }
    }
}

// ---------- LSTM recurrence ----------
// 128 CTAs x 4 batch rows. z^T[512 gates, n=8(4 used)] = U^T @ h^T via mma.
// U^T A-fragments live entirely in registers (loaded once). Smem: As staging
// [512][136] fp16, zbuf [512][6] fp32, hp [64][8] uint32 (half2 B-fragments).
template <int LAYER>
__global__ void __launch_bounds__(256, 1)
k_rnn(const float* __restrict__ Urec) {
    extern __shared__ char sm[];
    __half*   As = (__half*)sm;                                   // 139264 B
    float*    zb = (float*)(sm + 512 * 136 * 2);                  // 12288 B
    uint32_t* hp = (uint32_t*)(sm + 512 * 136 * 2 + 512 * 6 * 4); // 2048 B
    const int th = threadIdx.x, w = th >> 5, lane = th & 31;
    const int b0 = blockIdx.x * 4;

    // stage U^T: As[g][k] = U[k][g]
    for (int i = th; i < 512 * 128; i += 256) {
        int g = i >> 7, k = i & 127;
        As[g * 136 + k] = __float2half(Urec[(size_t)k * NG + g]);
    }
    for (int i = th; i < 64 * 8; i += 256) hp[i] = 0u;
    __syncthreads();

    // preload A fragments into registers: ua[mt][kt][4]
    uint32_t ua[4][8][4];
#pragma unroll
    for (int mt = 0; mt < 4; mt++) {
        int row = w * 64 + mt * 16 + (lane & 7) + ((lane >> 3) & 1) * 8;
#pragma unroll
        for (int kt = 0; kt < 8; kt++)
            ldsm4(ua[mt][kt], &As[row * 136 + kt * 16 + (lane >> 4) * 8]);
    }
    __syncthreads();

    const int bb = th & 3;    // batch lane within CTA
    const int up = th >> 2;   // u-pair 0..63
    float2 xi, xf, xg, xo;    // current-step xz (gates i,f,g,o for u=2up,2up+1)
    {
        const float* p = g_xz + ((size_t)(b0 + bb)) * NG;
        xi = *(const float2*)(p + 2 * up);
        xf = *(const float2*)(p + 128 + 2 * up);
        xg = *(const float2*)(p + 256 + 2 * up);
        xo = *(const float2*)(p + 384 + 2 * up);
    }
    float c0 = 0.f, c1 = 0.f;

    for (int t = 0; t < TT; t++) {
        // -------- phase 1: rec = U^T @ h^T --------
        float acc[4][4];
#pragma unroll
        for (int mt = 0; mt < 4; mt++)
#pragma unroll
            for (int q = 0; q < 4; q++) acc[mt][q] = 0.f;
#pragma unroll
        for (int kt = 0; kt < 8; kt++) {
            uint32_t bf0 = hp[(kt * 8 + (lane & 3)) * 8 + (lane >> 2)];
            uint32_t bf1 = hp[(kt * 8 + 4 + (lane & 3)) * 8 + (lane >> 2)];
#pragma unroll
            for (int mt = 0; mt < 4; mt++) mma16816(acc[mt], ua[mt][kt], bf0, bf1);
        }
        // prefetch next step's xz while mma drains
        float2 ni = xi, nf = xf, ng = xg, no = xo;
        if (t + 1 < TT) {
            const float* p = g_xz + ((size_t)(t + 1) * BB + b0 + bb) * NG;
            ni = *(const float2*)(p + 2 * up);
            nf = *(const float2*)(p + 128 + 2 * up);
            ng = *(const float2*)(p + 256 + 2 * up);
            no = *(const float2*)(p + 384 + 2 * up);
        }
        {
            int n = (lane & 3) * 2;
            if (n < 4) {
#pragma unroll
                for (int mt = 0; mt < 4; mt++) {
                    int g0 = w * 64 + mt * 16 + (lane >> 2);
                    *(float2*)&zb[g0 * 6 + n]       = make_float2(acc[mt][0], acc[mt][1]);
                    *(float2*)&zb[(g0 + 8) * 6 + n] = make_float2(acc[mt][2], acc[mt][3]);
                }
            }
        }
        __syncthreads();

        // -------- phase 2: elementwise (2 cells per thread) --------
        int u0 = 2 * up, u1 = 2 * up + 1;
        float i0 = sigm(zb[u0 * 6 + bb] + xi.x);
        float i1 = sigm(zb[u1 * 6 + bb] + xi.y);
        float f0 = sigm(zb[(128 + u0) * 6 + bb] + xf.x);
        float f1 = sigm(zb[(128 + u1) * 6 + bb] + xf.y);
        float g0 = tanhe(zb[(256 + u0) * 6 + bb] + xg.x);
        float g1 = tanhe(zb[(256 + u1) * 6 + bb] + xg.y);
        float o0 = sigm(zb[(384 + u0) * 6 + bb] + xo.x);
        float o1 = sigm(zb[(384 + u1) * 6 + bb] + xo.y);
        c0 = f0 * c0 + i0 * g0;
        c1 = f1 * c1 + i1 * g1;
        float h0 = o0 * tanhe(c0);
        float h1 = o1 * tanhe(c1);
        __half2 hh = __floats2half2_rn(h0, h1);
        hp[up * 8 + bb] = *(uint32_t*)&hh;
        if (LAYER == 0) {
            *(__half2*)&g_hs[((size_t)t * BB + b0 + bb) * UU + u0] = hh;
        } else if (t == TT - 1) {
            *(float2*)&g_hlast[(size_t)(b0 + bb) * UU + u0] = make_float2(h0, h1);
        }
        xi = ni; xf = nf; xg = ng; xo = no;
        __syncthreads();   // hp ready for next step; zb free for rewrite
    }
}

// ---------- dense: out[b] = relu(hlast[b,:] @ Wd + bd) ----------
__global__ void k_dense(const float* __restrict__ Wd, const float* __restrict__ bd,
                        float* __restrict__ out) {
    int b = blockIdx.x * blockDim.x + threadIdx.x;
    if (b >= BB) return;
    float acc = bd[0];
    const float* h = &g_hlast[(size_t)b * UU];
#pragma unroll 8
    for (int u = 0; u < UU; u++) acc = fmaf(h[u], Wd[u], acc);
    out[b] = fmaxf(acc, 0.f);
}

// ---------- launch ----------
extern "C" void kernel_launch(void* const* d_in, const int* in_sizes, int n_in,
                              void* d_out, int out_size) {
    const float* x  = (const float*)d_in[0];
    const float* W1 = (const float*)d_in[1];
    const float* U1 = (const float*)d_in[2];
    const float* b1 = (const float*)d_in[3];
    const float* W2 = (const float*)d_in[4];
    const float* U2 = (const float*)d_in[5];
    const float* b2 = (const float*)d_in[6];
    const float* Wd = (const float*)d_in[7];
    const float* bd = (const float*)d_in[8];
    float* out = (float*)d_out;

    const int SM_G64  = 32 * 520 * 4 + 64 * 72 * 2 + NG * 4;    // 77824
    const int SM_G128 = 64 * 520 * 4 + 64 * 136 * 2 + NG * 4;   // 152576
    const int SM_RNN  = 512 * 136 * 2 + 512 * 6 * 4 + 64 * 8 * 4; // 153600

    cudaFuncSetAttribute(k_gemm<64>,  cudaFuncAttributeMaxDynamicSharedMemorySize, SM_G64);
    cudaFuncSetAttribute(k_gemm<128>, cudaFuncAttributeMaxDynamicSharedMemorySize, SM_G128);
    cudaFuncSetAttribute(k_rnn<0>,    cudaFuncAttributeMaxDynamicSharedMemorySize, SM_RNN);
    cudaFuncSetAttribute(k_rnn<1>,    cudaFuncAttributeMaxDynamicSharedMemorySize, SM_RNN);

    __half* x16p;  cudaGetSymbolAddress((void**)&x16p, g_x16);
    float*  xzp;   cudaGetSymbolAddress((void**)&xzp,  g_xz);
    __half* hsp;   cudaGetSymbolAddress((void**)&hsp,  g_hs);

    k_prep<<<512, 256>>>(x);
    k_gemm<64><<<148, 256, SM_G64>>>(x16p, W1, b1, xzp, TB / 64);
    k_rnn<0><<<128, 256, SM_RNN>>>(U1);
    k_gemm<128><<<148, 256, SM_G128>>>(hsp, W2, b2, xzp, TB / 64);
    k_rnn<1><<<128, 256, SM_RNN>>>(U2);
    k_dense<<<4, 128>>>(Wd, bd, out);
}

// round 4
// speedup vs baseline: 1.4408x; 1.4408x over previous
#include <cuda_runtime.h>
#include <cuda_fp16.h>
#include <cstdint>

#define TT 256
#define BB 512
#define FF 64
#define UU 128
#define NG 512           // 4*U
#define TB (TT*BB)       // 131072

// ---------- static device scratch (no allocation) ----------
__device__ __half g_x16[(size_t)TB * FF];   // x time-major fp16 [t][b][f]
__device__ float  g_xz [(size_t)TB * NG];   // xz scratch fp32 (reused both layers)
__device__ __half g_hs [(size_t)TB * UU];   // layer-1 hidden states [t][b][u]
__device__ float  g_hlast[BB * UU];         // layer-2 final h

// ---------- helpers ----------
__device__ __forceinline__ void mma16816(float* d, const uint32_t* a, uint32_t b0, uint32_t b1) {
    asm volatile(
        "mma.sync.aligned.m16n8k16.row.col.f32.f16.f16.f32 "
        "{%0,%1,%2,%3}, {%4,%5,%6,%7}, {%8,%9}, {%0,%1,%2,%3};"
        : "+f"(d[0]), "+f"(d[1]), "+f"(d[2]), "+f"(d[3])
        : "r"(a[0]), "r"(a[1]), "r"(a[2]), "r"(a[3]), "r"(b0), "r"(b1));
}
__device__ __forceinline__ void ldsm4(uint32_t* a, const __half* p) {
    uint32_t addr = (uint32_t)__cvta_generic_to_shared(p);
    asm volatile("ldmatrix.sync.aligned.m8n8.x4.shared.b16 {%0,%1,%2,%3}, [%4];"
                 : "=r"(a[0]), "=r"(a[1]), "=r"(a[2]), "=r"(a[3]) : "r"(addr));
}
__device__ __forceinline__ float sigm(float x) {
    return __fdividef(1.f, 1.f + __expf(-x));
}
__device__ __forceinline__ float tanhe(float x) {
    return 1.f - 2.f * __fdividef(1.f, 1.f + __expf(2.f * x));
}

// ---------- convert x [B][T][F] fp32 -> [T][B][F] fp16 ----------
__global__ void k_prep(const float* __restrict__ x) {
    int n = TB * FF;
    for (int idx = blockIdx.x * blockDim.x + threadIdx.x; idx < n; idx += gridDim.x * blockDim.x) {
        int f = idx & 63;
        int b = (idx >> 6) & 511;
        int t = idx >> 15;
        g_x16[idx] = __float2half(x[((size_t)b * TT + t) * FF + f]);
    }
}

// ---------- GEMM: out[M][512] = A(fp16)[M][K] @ W(fp32)[K][512] + bias ----------
// tile M=64 x N=NT; 8 warps x NT/8 cols; 2 CTAs/SM for latency hiding.
template <int K, int NT>
__global__ void __launch_bounds__(256, 2)
k_gemm(const __half* __restrict__ A, const float* __restrict__ Wg,
       const float* __restrict__ bias, float* __restrict__ out, int Mtiles) {
    extern __shared__ char sm[];
    const int LDW = NT + 8;
    uint32_t* Wp = (uint32_t*)sm;                                // [K/2][LDW] half2
    __half*   As = (__half*)(sm + (K / 2) * LDW * 4);            // [64][K+8]
    const int ldA = K + 8;
    const int NS = 512 / NT;
    int tid = threadIdx.x, w = tid >> 5, lane = tid & 31;
    int n0 = (blockIdx.x % NS) * NT;

    // stage this CTA's N-slice of W, packed half2 along k
    for (int i = tid; i < (K / 2) * NT; i += 256) {
        int kk = i / NT, nl = i % NT, n = n0 + nl;
        __half2 h2 = __floats2half2_rn(Wg[(size_t)(2 * kk) * NG + n],
                                       Wg[(size_t)(2 * kk + 1) * NG + n]);
        Wp[kk * LDW + nl] = *(uint32_t*)&h2;
    }

    for (int tile = blockIdx.x / NS; tile < Mtiles; tile += gridDim.x / NS) {
        int m0 = tile * 64;
        __syncthreads();   // Wp ready (first iter) / As reuse guard
        for (int i = tid; i < 64 * (K / 8); i += 256) {
            int r = i / (K / 8), c = (i % (K / 8)) * 8;
            *(uint4*)&As[r * ldA + c] = *(const uint4*)&A[(size_t)(m0 + r) * K + c];
        }
        __syncthreads();

        float acc[4][4][4];
#pragma unroll
        for (int mt = 0; mt < 4; mt++)
#pragma unroll
            for (int nt = 0; nt < 4; nt++)
#pragma unroll
                for (int q = 0; q < 4; q++) acc[mt][nt][q] = 0.f;

#pragma unroll
        for (int kt = 0; kt < K / 16; kt++) {
            uint32_t a[4][4];
#pragma unroll
            for (int mt = 0; mt < 4; mt++) {
                int row = mt * 16 + (lane & 7) + ((lane >> 3) & 1) * 8;
                int col = kt * 16 + (lane >> 4) * 8;
                ldsm4(a[mt], &As[row * ldA + col]);
            }
            int c4 = lane & 3;
#pragma unroll
            for (int nt = 0; nt < 4; nt++) {
                int nl = w * 32 + nt * 8 + (lane >> 2);
                uint32_t b0 = Wp[(kt * 8 + c4) * LDW + nl];
                uint32_t b1 = Wp[(kt * 8 + 4 + c4) * LDW + nl];
#pragma unroll
                for (int mt = 0; mt < 4; mt++) mma16816(acc[mt][nt], a[mt], b0, b1);
            }
        }
#pragma unroll
        for (int mt = 0; mt < 4; mt++) {
            int r0 = m0 + mt * 16 + (lane >> 2);
#pragma unroll
            for (int nt = 0; nt < 4; nt++) {
                int cc = n0 + w * 32 + nt * 8 + (lane & 3) * 2;
                float bb0 = __ldg(&bias[cc]), bb1 = __ldg(&bias[cc + 1]);
                *(float2*)&out[(size_t)r0 * NG + cc] =
                    make_float2(acc[mt][nt][0] + bb0, acc[mt][nt][1] + bb1);
                *(float2*)&out[(size_t)(r0 + 8) * NG + cc] =
                    make_float2(acc[mt][nt][2] + bb0, acc[mt][nt][3] + bb1);
            }
        }
    }
}

// ---------- LSTM recurrence ----------
// 128 CTAs x 4 batch rows. Gate-permuted rows: warp w owns units [w*16,w*16+16),
// mt-block = gate (0=i,1=f,2=g,3=o). After mma the 4 gates of each cell are in
// registers; 16 SHFLs spread 64 cells/warp to 2 cells/thread. hp double-buffered
// -> ONE barrier per step.
template <int LAYER>
__global__ void __launch_bounds__(256, 1)
k_rnn(const float* __restrict__ Urec) {
    extern __shared__ char sm[];
    __half*   As = (__half*)sm;                         // [512][136] = 139264 B
    uint32_t* hp = (uint32_t*)(sm + 512 * 136 * 2);     // 2 x [64][8] = 4096 B
    const int th = threadIdx.x, w = th >> 5, lane = th & 31;
    const int b0 = blockIdx.x * 4;

    // stage permuted U^T: As[w*64 + mt*16 + r][k] = U[k][mt*128 + w*16 + r]
    for (int i = th; i < 512 * 128; i += 256) {
        int g = i >> 7, k = i & 127;
        int G = ((g >> 4) & 3) * 128 + (g >> 6) * 16 + (g & 15);
        As[g * 136 + k] = __float2half(Urec[(size_t)k * NG + G]);
    }
    for (int i = th; i < 1024; i += 256) hp[i] = 0u;
    __syncthreads();

    // preload A fragments into registers (static across all steps)
    uint32_t ua[4][8][4];
#pragma unroll
    for (int mt = 0; mt < 4; mt++) {
        int row = w * 64 + mt * 16 + (lane & 7) + ((lane >> 3) & 1) * 8;
#pragma unroll
        for (int kt = 0; kt < 8; kt++)
            ldsm4(ua[mt][kt], &As[row * 136 + kt * 16 + (lane >> 4) * 8]);
    }
    __syncthreads();

    const int rp = lane & 15;           // unit offset within warp
    const int qq = lane >> 4;           // batch-pair select
    const int u  = w * 16 + rp;         // this thread's unit
    const int src = ((lane & 7) << 2) | qq;
    const bool hi = (lane & 8) != 0;

    // current-step xz: [gate][batch j] for batches b0+2qq+{0,1}
    float xc[4][2];
    {
        const float* p = g_xz + ((size_t)(b0 + 2 * qq)) * NG + u;
#pragma unroll
        for (int mt = 0; mt < 4; mt++) {
            xc[mt][0] = p[mt * 128];
            xc[mt][1] = p[NG + mt * 128];
        }
    }
    float cst[2] = {0.f, 0.f};
    int ph = 0;

    for (int t = 0; t < TT; t++) {
        // ---- phase 1: z = U^T @ h^T (reads hp[ph]) ----
        float acc[4][4];
#pragma unroll
        for (int mt = 0; mt < 4; mt++)
#pragma unroll
            for (int q = 0; q < 4; q++) acc[mt][q] = 0.f;
        const uint32_t* hpc = hp + ph * 512;
#pragma unroll
        for (int kt = 0; kt < 8; kt++) {
            uint32_t bf0 = hpc[(kt * 8 + (lane & 3)) * 8 + (lane >> 2)];
            uint32_t bf1 = hpc[(kt * 8 + 4 + (lane & 3)) * 8 + (lane >> 2)];
#pragma unroll
            for (int mt = 0; mt < 4; mt++) mma16816(acc[mt], ua[mt][kt], bf0, bf1);
        }

        // prefetch next step's xz
        float xn[4][2];
        if (t + 1 < TT) {
            const float* p = g_xz + ((size_t)(t + 1) * BB + b0 + 2 * qq) * NG + u;
#pragma unroll
            for (int mt = 0; mt < 4; mt++) {
                xn[mt][0] = p[mt * 128];
                xn[mt][1] = p[NG + mt * 128];
            }
        }

        // ---- redistribute: lane gets 4 gates x 2 batches for its unit ----
        float za[4][2];
#pragma unroll
        for (int mt = 0; mt < 4; mt++) {
            float lo0 = __shfl_sync(0xffffffffu, acc[mt][0], src);
            float lo1 = __shfl_sync(0xffffffffu, acc[mt][1], src);
            float hi0 = __shfl_sync(0xffffffffu, acc[mt][2], src);
            float hi1 = __shfl_sync(0xffffffffu, acc[mt][3], src);
            za[mt][0] = hi ? hi0 : lo0;
            za[mt][1] = hi ? hi1 : lo1;
        }

        // ---- phase 2: elementwise, fully in registers ----
        __half* hpn = (__half*)(hp + (ph ^ 1) * 512);
#pragma unroll
        for (int j = 0; j < 2; j++) {
            float iv = sigm(za[0][j] + xc[0][j]);
            float fv = sigm(za[1][j] + xc[1][j]);
            float gv = tanhe(za[2][j] + xc[2][j]);
            float ov = sigm(za[3][j] + xc[3][j]);
            cst[j] = fv * cst[j] + iv * gv;
            float hv = ov * tanhe(cst[j]);
            int bbl = 2 * qq + j;
            hpn[((u >> 1) * 8 + bbl) * 2 + (u & 1)] = __float2half(hv);
            if (LAYER == 0) {
                g_hs[((size_t)t * BB + b0 + bbl) * UU + u] = __float2half(hv);
            } else if (t == TT - 1) {
                g_hlast[(size_t)(b0 + bbl) * UU + u] = hv;
            }
        }
#pragma unroll
        for (int mt = 0; mt < 4; mt++) { xc[mt][0] = xn[mt][0]; xc[mt][1] = xn[mt][1]; }
        __syncthreads();   // hp[ph^1] visible for next step
        ph ^= 1;
    }
}

// ---------- dense: out[b] = relu(hlast[b,:] @ Wd + bd) ----------
__global__ void k_dense(const float* __restrict__ Wd, const float* __restrict__ bd,
                        float* __restrict__ out) {
    int b = blockIdx.x * blockDim.x + threadIdx.x;
    if (b >= BB) return;
    float acc = bd[0];
    const float* h = &g_hlast[(size_t)b * UU];
#pragma unroll 8
    for (int u = 0; u < UU; u++) acc = fmaf(h[u], Wd[u], acc);
    out[b] = fmaxf(acc, 0.f);
}

// ---------- launch ----------
extern "C" void kernel_launch(void* const* d_in, const int* in_sizes, int n_in,
                              void* d_out, int out_size) {
    const float* x  = (const float*)d_in[0];
    const float* W1 = (const float*)d_in[1];
    const float* U1 = (const float*)d_in[2];
    const float* b1 = (const float*)d_in[3];
    const float* W2 = (const float*)d_in[4];
    const float* U2 = (const float*)d_in[5];
    const float* b2 = (const float*)d_in[6];
    const float* Wd = (const float*)d_in[7];
    const float* bd = (const float*)d_in[8];
    float* out = (float*)d_out;

    const int SM_G64  = 32 * 264 * 4 + 64 * 72 * 2;        // 43008
    const int SM_G128 = 64 * 264 * 4 + 64 * 136 * 2;       // 84992
    const int SM_RNN  = 512 * 136 * 2 + 2 * 512 * 4;       // 143360

    cudaFuncSetAttribute((const void*)k_gemm<64, 256>,
                         cudaFuncAttributeMaxDynamicSharedMemorySize, SM_G64);
    cudaFuncSetAttribute((const void*)k_gemm<128, 256>,
                         cudaFuncAttributeMaxDynamicSharedMemorySize, SM_G128);
    cudaFuncSetAttribute((const void*)k_rnn<0>,
                         cudaFuncAttributeMaxDynamicSharedMemorySize, SM_RNN);
    cudaFuncSetAttribute((const void*)k_rnn<1>,
                         cudaFuncAttributeMaxDynamicSharedMemorySize, SM_RNN);

    __half* x16p;  cudaGetSymbolAddress((void**)&x16p, g_x16);
    float*  xzp;   cudaGetSymbolAddress((void**)&xzp,  g_xz);
    __half* hsp;   cudaGetSymbolAddress((void**)&hsp,  g_hs);

    k_prep<<<512, 256>>>(x);
    k_gemm<64, 256><<<296, 256, SM_G64>>>(x16p, W1, b1, xzp, TB / 64);
    k_rnn<0><<<128, 256, SM_RNN>>>(U1);
    k_gemm<128, 256><<<296, 256, SM_G128>>>(hsp, W2, b2, xzp, TB / 64);
    k_rnn<1><<<128, 256, SM_RNN>>>(U2);
    k_dense<<<4, 128>>>(Wd, bd, out);
}